// round 1
// baseline (speedup 1.0000x reference)
#include <cuda_runtime.h>
#include <stdint.h>

// Lukasiewicz t-norm feature expansion:
//   out[:, 0:16)    = x
//   out[:, 16:136)  = max(x[i]+x[j] - 1, 0)          for i<j   (120 pairs)
//   out[:, 136:696) = max(x[i]+x[j]+x[k] - 2, 0)     for i<j<k (560 triples)
// N = 131072 rows, 16 input cols, 696 output cols. Pure store-BW bound.

#define N_ROWS   131072
#define N_IN     16
#define OUT_C    696
#define OUT_V4   174           // 696 / 4
#define WARPS_PB 8             // rows per block
#define BLOCK_T  (WARPS_PB * 32)

__global__ void __launch_bounds__(BLOCK_T)
luk_kernel(const float* __restrict__ x, float* __restrict__ out)
{
    // Column descriptor table: (k<<15)|(a<<10)|(b<<5)|c, unused slots point to
    // xs[..][16] which holds 0.0f, so every column is branch-free:
    //   out = max(x[a]+x[b]+x[c] + (1-k), 0)
    __shared__ uint32_t tab[OUT_C];
    __shared__ float    xs[WARPS_PB][17];

    const int tid = threadIdx.x;

    // Build table (lexicographic unranking — matches itertools.combinations)
    for (int c = tid; c < OUT_C; c += BLOCK_T) {
        int a, b, d, k;
        if (c < 16) {
            k = 1; a = c; b = 16; d = 16;
        } else if (c < 136) {
            k = 2;
            int rem = c - 16, i = 0;
            while (rem >= 15 - i) { rem -= 15 - i; ++i; }
            a = i; b = i + 1 + rem; d = 16;
        } else {
            k = 3;
            int rem = c - 136, i = 0;
            for (;;) {
                int cnt = (15 - i) * (14 - i) / 2;
                if (rem < cnt) break;
                rem -= cnt; ++i;
            }
            int j = i + 1;
            while (rem >= 15 - j) { rem -= 15 - j; ++j; }
            a = i; b = j; d = j + 1 + rem;
        }
        tab[c] = (uint32_t)((k << 15) | (a << 10) | (b << 5) | d);
    }

    const int w    = tid >> 5;
    const int lane = tid & 31;
    const long long row = (long long)blockIdx.x * WARPS_PB + w;

    // Stage this warp's row into shared (slot 16 = 0 for the dummy index)
    if (lane < 16)       xs[w][lane] = x[row * N_IN + lane];
    else if (lane == 16) xs[w][16]   = 0.0f;
    __syncthreads();

    const float* __restrict__ xr = xs[w];
    float4* __restrict__ orow = (float4*)(out + row * (long long)OUT_C);
    const uint4* __restrict__ tab4 = (const uint4*)tab;

    // 174 float4 outputs per row, striped across the warp -> coalesced STG.128
    for (int v = lane; v < OUT_V4; v += 32) {
        const uint4 e = tab4[v];
        float4 r;
        {
            uint32_t t = e.x;
            float s = xr[(t >> 10) & 31] + xr[(t >> 5) & 31] + xr[t & 31];
            r.x = fmaxf(s + (1.0f - (float)(int)((t >> 15) & 3)), 0.0f);
        }
        {
            uint32_t t = e.y;
            float s = xr[(t >> 10) & 31] + xr[(t >> 5) & 31] + xr[t & 31];
            r.y = fmaxf(s + (1.0f - (float)(int)((t >> 15) & 3)), 0.0f);
        }
        {
            uint32_t t = e.z;
            float s = xr[(t >> 10) & 31] + xr[(t >> 5) & 31] + xr[t & 31];
            r.z = fmaxf(s + (1.0f - (float)(int)((t >> 15) & 3)), 0.0f);
        }
        {
            uint32_t t = e.w;
            float s = xr[(t >> 10) & 31] + xr[(t >> 5) & 31] + xr[t & 31];
            r.w = fmaxf(s + (1.0f - (float)(int)((t >> 15) & 3)), 0.0f);
        }
        orow[v] = r;
    }
}

extern "C" void kernel_launch(void* const* d_in, const int* in_sizes, int n_in,
                              void* d_out, int out_size)
{
    const float* x = (const float*)d_in[0];
    float* out = (float*)d_out;
    (void)in_sizes; (void)n_in; (void)out_size;

    const int grid = N_ROWS / WARPS_PB;   // 16384 blocks, 8 rows each
    luk_kernel<<<grid, BLOCK_T>>>(x, out);
}

// round 4
// speedup vs baseline: 1.6969x; 1.6969x over previous
#include <cuda_runtime.h>
#include <stdint.h>

// Lukasiewicz t-norm feature expansion, compile-time-unrolled.
//   out[:, 0:16)    = x
//   out[:, 16:136)  = max(x[i]+x[j] - 1, 0)       i<j    (120)
//   out[:, 136:696) = max(x[i]+x[j]+x[k] - 2, 0)  i<j<k  (560)
// N = 131072 rows, 16 in cols, 696 out cols (= 174 float4).
//
// Layout: 1 lane = 1 row (x in registers, all indices compile-time via
// __device__ constexpr table + full unroll -> pure FADD/FMNMX, no decode).
// Output staged per-warp in shared in 16-float4 column chunks, then copied
// out coalesced (half-warp per row, immediate-offset LDS.128/STG.128).

#define N_ROWS   131072
#define OUT_V4   174
#define CH_V4    16            // float4 columns per chunk
#define NCHUNK   11            // 10 full chunks + 1 overlapped tail (base 158)
#define WARPS_PB 4
#define BLOCK_T  (WARPS_PB * 32)

struct TabT {
    unsigned char k[696], a[696], b[696], c[696];
};

__host__ __device__ constexpr TabT make_tab() {
    TabT t{};
    int n = 0;
    for (int i = 0; i < 16; ++i) {
        t.k[n] = 1; t.a[n] = (unsigned char)i; t.b[n] = 0; t.c[n] = 0; ++n;
    }
    for (int i = 0; i < 16; ++i)
        for (int j = i + 1; j < 16; ++j) {
            t.k[n] = 2; t.a[n] = (unsigned char)i; t.b[n] = (unsigned char)j;
            t.c[n] = 0; ++n;
        }
    for (int i = 0; i < 16; ++i)
        for (int j = i + 1; j < 16; ++j)
            for (int l = j + 1; l < 16; ++l) {
                t.k[n] = 3; t.a[n] = (unsigned char)i; t.b[n] = (unsigned char)j;
                t.c[n] = (unsigned char)l; ++n;
            }
    return t;
}
__device__ constexpr TabT TAB = make_tab();

__global__ void __launch_bounds__(BLOCK_T)
luk_kernel(const float4* __restrict__ x4, float4* __restrict__ out4)
{
    const int tid  = threadIdx.x;
    const int warp = tid >> 5;
    const int lane = tid & 31;

    const long long tileRow = ((long long)blockIdx.x * WARPS_PB + warp) * 32;
    const long long myRow   = tileRow + lane;

    // Load this lane's row (16 floats) into registers.
    float xv[16];
    {
        const float4 v0 = x4[myRow * 4 + 0];
        const float4 v1 = x4[myRow * 4 + 1];
        const float4 v2 = x4[myRow * 4 + 2];
        const float4 v3 = x4[myRow * 4 + 3];
        xv[0]=v0.x; xv[1]=v0.y; xv[2]=v0.z;  xv[3]=v0.w;
        xv[4]=v1.x; xv[5]=v1.y; xv[6]=v1.z;  xv[7]=v1.w;
        xv[8]=v2.x; xv[9]=v2.y; xv[10]=v2.z; xv[11]=v2.w;
        xv[12]=v3.x; xv[13]=v3.y; xv[14]=v3.z; xv[15]=v3.w;
    }
    float xm1[16], xm2[16];
#pragma unroll
    for (int i = 0; i < 16; ++i) { xm1[i] = xv[i] - 1.0f; xm2[i] = xv[i] - 2.0f; }

    // Per-warp staging buffer: [32 rows][17 float4] (stride 68 floats ->
    // bank-conflict-free for both the compute-phase STS.128 and copy-out LDS.128)
    __shared__ float4 sh[WARPS_PB][32][CH_V4 + 1];
    float4* __restrict__ mysh = &sh[warp][lane][0];

    // Per-lane output base pointer for the copy-out phase (immediate offsets).
    float4* __restrict__ opBase =
        out4 + (tileRow + (lane >> 4)) * OUT_V4 + (lane & 15);

#pragma unroll
    for (int ch = 0; ch < NCHUNK; ++ch) {
        const int baseV4 = (ch == NCHUNK - 1) ? (OUT_V4 - CH_V4) : ch * CH_V4;
        const int base   = baseV4 * 4;

        // ---- compute phase: this lane's row, 64 columns, all-register ----
#pragma unroll
        for (int v = 0; v < CH_V4; ++v) {
            float r[4];
#pragma unroll
            for (int e = 0; e < 4; ++e) {
                const int col = base + v * 4 + e;
                const int K = TAB.k[col];
                const int A = TAB.a[col];
                const int B = TAB.b[col];
                const int C = TAB.c[col];
                if (K == 1)      r[e] = xv[A];
                else if (K == 2) r[e] = fmaxf(xv[A] + xm1[B], 0.0f);
                else             r[e] = fmaxf(xv[A] + xv[B] + xm2[C], 0.0f);
            }
            mysh[v] = make_float4(r[0], r[1], r[2], r[3]);
        }
        __syncwarp();

        // ---- copy-out phase: half-warp per row, coalesced 256B bursts ----
#pragma unroll
        for (int t = 0; t < 16; ++t) {
            const int rr = t * 2 + (lane >> 4);
            const float4 val = sh[warp][rr][lane & 15];
            opBase[(long long)t * (2 * OUT_V4) + baseV4] = val;
        }
        __syncwarp();
    }
}

extern "C" void kernel_launch(void* const* d_in, const int* in_sizes, int n_in,
                              void* d_out, int out_size)
{
    const float4* x4 = (const float4*)d_in[0];
    float4* out4 = (float4*)d_out;
    (void)in_sizes; (void)n_in; (void)out_size;

    const int grid = N_ROWS / (WARPS_PB * 32);   // 1024 blocks
    luk_kernel<<<grid, BLOCK_T>>>(x4, out4);
}